// round 1
// baseline (speedup 1.0000x reference)
#include <cuda_runtime.h>
#include <cstdint>
#include <cstddef>

// Problem constants
constexpr int cB   = 256;
constexpr int cT   = 128;
constexpr int cOBS = 512;
constexpr int cE   = 1024;
constexpr int cH   = 1024;
constexpr int cA   = 64;
constexpr int cBT  = cB * cT;        // 32768
constexpr int cG   = 4 * cH;         // 4096

// Output layout (flat tuple order): logits, values, obs_pred, rew_pred, hT, cT
constexpr size_t OFF_LOGITS = 0;
constexpr size_t OFF_VAL    = OFF_LOGITS + (size_t)cBT * cA;        // 2,097,152
constexpr size_t OFF_OBS    = OFF_VAL + (size_t)cBT;                // 2,129,920
constexpr size_t OFF_REW    = OFF_OBS + (size_t)cBT * cOBS;         // 18,907,136
constexpr size_t OFF_HT     = OFF_REW + (size_t)cBT;                // 18,939,904
constexpr size_t OFF_CT     = OFF_HT + (size_t)cB * cH;             // 19,202,048

// Scratch (device globals; no runtime allocation allowed)
__device__ float g_enc1[(size_t)cBT * cE];   // encoder hidden 1, reused as LN output x
__device__ float g_enc2[(size_t)cBT * cE];   // encoder output
__device__ float g_gx[(size_t)cBT * cG];     // [T, B, 4H]
__device__ float g_hseq[(size_t)cBT * cH];   // [B, T, H]
__device__ float g_gates[(size_t)cB * cG];   // per-step gates
__device__ float g_hbuf[2][(size_t)cB * cH];
__device__ float g_cbuf[2][(size_t)cB * cH];

// ---------------------------------------------------------------------------
// Generic SGEMM: C[M,N] = A[M,K] (row-major) * B, with epilogues.
// TRANSB=false: B is [K,N] row-major. TRANSB=true: B is [N,K] row-major.
// EPI: 0 = +bias ; 1 = silu(+bias) ; 2 = +bias+bias2, row swizzled r->(r%T)*Bsw+r/T
//      3 = +Cadd[row*N+col]  (residual)
// Requires M%BM==0, N%BN==0, K%BK==0.
// ---------------------------------------------------------------------------
template<int BM, int BN, int BK, int TM, int TN, bool TRANSB, int EPI>
__global__ void __launch_bounds__((BM/TM)*(BN/TN))
sgemm_k(const float* __restrict__ Ag, const float* __restrict__ Bg,
        float* __restrict__ Cg,
        const float* __restrict__ bias, const float* __restrict__ bias2,
        const float* __restrict__ Cadd,
        int M, int N, int K, int Tsw, int Bsw)
{
    constexpr int NT = (BM/TM)*(BN/TN);
    constexpr int LA = (BM*BK)/(4*NT);
    constexpr int LB = (BK*BN)/(4*NT);
    static_assert(LA >= 1 && LB >= 1, "tile too small");

    __shared__ float As[2][BK][BM];
    __shared__ float Bs[2][BK][BN];

    const int tid = threadIdx.x;
    const int tr  = tid / (BN/TN);
    const int tc  = tid % (BN/TN);
    const int m0  = blockIdx.y * BM;
    const int n0  = blockIdx.x * BN;

    float acc[TM][TN];
#pragma unroll
    for (int i = 0; i < TM; i++)
#pragma unroll
        for (int j = 0; j < TN; j++) acc[i][j] = 0.f;

    auto ldg_tiles = [&](int k0, float4 (&ar)[LA], float4 (&br)[LB]) {
#pragma unroll
        for (int p = 0; p < LA; p++) {
            int i = p*NT + tid;
            int row = i / (BK/4), c4 = i % (BK/4);
            ar[p] = *reinterpret_cast<const float4*>(Ag + (size_t)(m0+row)*K + k0 + c4*4);
        }
        if (!TRANSB) {
#pragma unroll
            for (int p = 0; p < LB; p++) {
                int i = p*NT + tid;
                int row = i / (BN/4), c4 = i % (BN/4);
                br[p] = *reinterpret_cast<const float4*>(Bg + (size_t)(k0+row)*N + n0 + c4*4);
            }
        } else {
#pragma unroll
            for (int p = 0; p < LB; p++) {
                int i = p*NT + tid;
                int row = i / (BK/4), c4 = i % (BK/4);
                br[p] = *reinterpret_cast<const float4*>(Bg + (size_t)(n0+row)*K + k0 + c4*4);
            }
        }
    };

    auto sts_tiles = [&](int buf, const float4 (&ar)[LA], const float4 (&br)[LB]) {
#pragma unroll
        for (int p = 0; p < LA; p++) {
            int i = p*NT + tid;
            int row = i / (BK/4), c4 = i % (BK/4);
            As[buf][c4*4+0][row] = ar[p].x;
            As[buf][c4*4+1][row] = ar[p].y;
            As[buf][c4*4+2][row] = ar[p].z;
            As[buf][c4*4+3][row] = ar[p].w;
        }
        if (!TRANSB) {
#pragma unroll
            for (int p = 0; p < LB; p++) {
                int i = p*NT + tid;
                int row = i / (BN/4), c4 = i % (BN/4);
                *reinterpret_cast<float4*>(&Bs[buf][row][c4*4]) = br[p];
            }
        } else {
#pragma unroll
            for (int p = 0; p < LB; p++) {
                int i = p*NT + tid;
                int row = i / (BK/4), c4 = i % (BK/4);
                Bs[buf][c4*4+0][row] = br[p].x;
                Bs[buf][c4*4+1][row] = br[p].y;
                Bs[buf][c4*4+2][row] = br[p].z;
                Bs[buf][c4*4+3][row] = br[p].w;
            }
        }
    };

    {
        float4 ar[LA], br[LB];
        ldg_tiles(0, ar, br);
        sts_tiles(0, ar, br);
    }
    __syncthreads();

    const int NKT = K / BK;
    for (int kt = 0; kt < NKT; ++kt) {
        const int cur = kt & 1;
        float4 ar[LA], br[LB];
        if (kt + 1 < NKT) ldg_tiles((kt+1)*BK, ar, br);

#pragma unroll
        for (int k = 0; k < BK; k++) {
            float a[TM], b[TN];
#pragma unroll
            for (int i = 0; i < TM; i += 4) {
                float4 v = *reinterpret_cast<const float4*>(&As[cur][k][tr*TM + i]);
                a[i] = v.x; a[i+1] = v.y; a[i+2] = v.z; a[i+3] = v.w;
            }
#pragma unroll
            for (int j = 0; j < TN; j += 4) {
                float4 v = *reinterpret_cast<const float4*>(&Bs[cur][k][tc*TN + j]);
                b[j] = v.x; b[j+1] = v.y; b[j+2] = v.z; b[j+3] = v.w;
            }
#pragma unroll
            for (int i = 0; i < TM; i++)
#pragma unroll
                for (int j = 0; j < TN; j++)
                    acc[i][j] = fmaf(a[i], b[j], acc[i][j]);
        }

        if (kt + 1 < NKT) sts_tiles(cur ^ 1, ar, br);
        __syncthreads();
    }

    // Epilogue
#pragma unroll
    for (int i = 0; i < TM; i++) {
        int row = m0 + tr*TM + i;
        size_t orow = (EPI == 2) ? (size_t)((row % Tsw) * Bsw + row / Tsw) : (size_t)row;
#pragma unroll
        for (int j = 0; j < TN; j += 4) {
            int col = n0 + tc*TN + j;
            float tv[4];
#pragma unroll
            for (int q = 0; q < 4; q++) {
                float t = acc[i][j+q];
                if (EPI != 3 && bias) t += bias[col+q];
                if (EPI == 2)         t += bias2[col+q];
                if (EPI == 3)         t += Cadd[(size_t)row*N + col + q];
                if (EPI == 1)         t = t / (1.f + expf(-t));   // SiLU
                tv[q] = t;
            }
            float4 v; v.x = tv[0]; v.y = tv[1]; v.z = tv[2]; v.w = tv[3];
            *reinterpret_cast<float4*>(Cg + orow*(size_t)N + col) = v;
        }
    }
}

// ---------------------------------------------------------------------------
__device__ __forceinline__ float sigmoidf_(float x) { return 1.f / (1.f + expf(-x)); }

__global__ void lstm_cell_k(const float* __restrict__ gates,
                            const float* __restrict__ c_in,
                            float* __restrict__ c_out,
                            float* __restrict__ h_out,
                            float* __restrict__ h_seq, int t)
{
    int idx = blockIdx.x * blockDim.x + threadIdx.x;
    if (idx >= cB * cH) return;
    int b = idx / cH, j = idx % cH;
    const float* g = gates + (size_t)b * cG;
    float ig = sigmoidf_(g[j]);
    float fg = sigmoidf_(g[cH + j]);
    float gg = tanhf(g[2*cH + j]);
    float og = sigmoidf_(g[3*cH + j]);
    float c  = fg * c_in[idx] + ig * gg;
    float h  = og * tanhf(c);
    c_out[idx] = c;
    h_out[idx] = h;
    h_seq[((size_t)b * cT + t) * cH + j] = h;
}

__global__ void layernorm_k(const float* __restrict__ in, float* __restrict__ out,
                            const float* __restrict__ gw, const float* __restrict__ bw)
{
    const int row = blockIdx.x;
    const float* x = in  + (size_t)row * cH;
    float*       y = out + (size_t)row * cH;
    float s = 0.f, ss = 0.f;
    for (int i = threadIdx.x * 4; i < cH; i += blockDim.x * 4) {
        float4 v = *reinterpret_cast<const float4*>(x + i);
        s  += v.x + v.y + v.z + v.w;
        ss += v.x*v.x + v.y*v.y + v.z*v.z + v.w*v.w;
    }
    __shared__ float red[64];
    for (int o = 16; o > 0; o >>= 1) {
        s  += __shfl_xor_sync(0xffffffffu, s,  o);
        ss += __shfl_xor_sync(0xffffffffu, ss, o);
    }
    int wid = threadIdx.x / 32, lane = threadIdx.x % 32;
    if (lane == 0) { red[wid] = s; red[32 + wid] = ss; }
    __syncthreads();
    if (threadIdx.x < 32) {
        int nw = blockDim.x / 32;
        float a = (threadIdx.x < nw) ? red[threadIdx.x]      : 0.f;
        float b = (threadIdx.x < nw) ? red[32 + threadIdx.x] : 0.f;
        for (int o = 16; o > 0; o >>= 1) {
            a += __shfl_xor_sync(0xffffffffu, a, o);
            b += __shfl_xor_sync(0xffffffffu, b, o);
        }
        if (threadIdx.x == 0) { red[0] = a; red[1] = b; }
    }
    __syncthreads();
    float mu   = red[0] / cH;
    float var  = red[1] / cH - mu * mu;
    float rstd = rsqrtf(var + 1e-5f);
    for (int i = threadIdx.x * 4; i < cH; i += blockDim.x * 4) {
        float4 v  = *reinterpret_cast<const float4*>(x + i);
        float4 gv = *reinterpret_cast<const float4*>(gw + i);
        float4 bv = *reinterpret_cast<const float4*>(bw + i);
        float4 o;
        o.x = (v.x - mu) * rstd * gv.x + bv.x;
        o.y = (v.y - mu) * rstd * gv.y + bv.y;
        o.z = (v.z - mu) * rstd * gv.z + bv.z;
        o.w = (v.w - mu) * rstd * gv.w + bv.w;
        *reinterpret_cast<float4*>(y + i) = o;
    }
}

// values = x @ Wc + bc ; rew = x @ Wr + br  (one warp per row, shared x reads)
__global__ void dual_gemv_k(const float* __restrict__ x,
                            const float* __restrict__ wc, const float* __restrict__ wr,
                            const float* __restrict__ bc, const float* __restrict__ br,
                            float* __restrict__ outv, float* __restrict__ outr)
{
    int warp = (blockIdx.x * blockDim.x + threadIdx.x) / 32;
    int lane = threadIdx.x % 32;
    if (warp >= cBT) return;
    const float* xr = x + (size_t)warp * cH;
    float sc = 0.f, sr = 0.f;
    for (int i = lane * 4; i < cH; i += 128) {
        float4 xv = *reinterpret_cast<const float4*>(xr + i);
        float4 cv = *reinterpret_cast<const float4*>(wc + i);
        float4 rv = *reinterpret_cast<const float4*>(wr + i);
        sc += xv.x*cv.x + xv.y*cv.y + xv.z*cv.z + xv.w*cv.w;
        sr += xv.x*rv.x + xv.y*rv.y + xv.z*rv.z + xv.w*rv.w;
    }
    for (int o = 16; o > 0; o >>= 1) {
        sc += __shfl_xor_sync(0xffffffffu, sc, o);
        sr += __shfl_xor_sync(0xffffffffu, sr, o);
    }
    if (lane == 0) {
        outv[warp] = sc + bc[0];
        outr[warp] = sr + br[0];
    }
}

__global__ void copy2_k(const float* __restrict__ a, const float* __restrict__ b,
                        float* __restrict__ oa, float* __restrict__ ob, int n)
{
    int i = blockIdx.x * blockDim.x + threadIdx.x;
    if (i < n) { oa[i] = a[i]; ob[i] = b[i]; }
}

// ---------------------------------------------------------------------------
extern "C" void kernel_launch(void* const* d_in, const int* in_sizes, int n_in,
                              void* d_out, int out_size)
{
    const float* obs   = (const float*)d_in[0];
    const float* h0    = (const float*)d_in[1];
    const float* c0    = (const float*)d_in[2];
    const float* W1    = (const float*)d_in[3];
    const float* b1    = (const float*)d_in[4];
    const float* W2    = (const float*)d_in[5];
    const float* b2    = (const float*)d_in[6];
    const float* w_ih  = (const float*)d_in[7];
    const float* w_hh  = (const float*)d_in[8];
    const float* b_ih  = (const float*)d_in[9];
    const float* b_hh  = (const float*)d_in[10];
    const float* ln_g  = (const float*)d_in[11];
    const float* ln_b  = (const float*)d_in[12];
    const float* Wa    = (const float*)d_in[13];
    const float* ba    = (const float*)d_in[14];
    const float* Wc    = (const float*)d_in[15];
    const float* bc    = (const float*)d_in[16];
    const float* Wobs  = (const float*)d_in[17];
    const float* bobs  = (const float*)d_in[18];
    const float* Wr    = (const float*)d_in[19];
    const float* br    = (const float*)d_in[20];
    float* out = (float*)d_out;

    float *enc1, *enc2, *gx, *hseq, *gates, *hb, *cb;
    cudaGetSymbolAddress((void**)&enc1,  g_enc1);
    cudaGetSymbolAddress((void**)&enc2,  g_enc2);
    cudaGetSymbolAddress((void**)&gx,    g_gx);
    cudaGetSymbolAddress((void**)&hseq,  g_hseq);
    cudaGetSymbolAddress((void**)&gates, g_gates);
    cudaGetSymbolAddress((void**)&hb,    g_hbuf);
    cudaGetSymbolAddress((void**)&cb,    g_cbuf);
    float* hbuf[2] = { hb, hb + (size_t)cB * cH };
    float* cbuf[2] = { cb, cb + (size_t)cB * cH };

    // 1) enc1 = silu(obs @ W1 + b1)   [32768,512]x[512,1024]
    {
        dim3 grid(cE/128, cBT/128);
        sgemm_k<128,128,16,8,8,false,1><<<grid, 256>>>(
            obs, W1, enc1, b1, nullptr, nullptr, cBT, cE, cOBS, 0, 0);
    }
    // 2) enc2 = silu(enc1 @ W2 + b2)  [32768,1024]x[1024,1024]
    {
        dim3 grid(cE/128, cBT/128);
        sgemm_k<128,128,16,8,8,false,1><<<grid, 256>>>(
            enc1, W2, enc2, b2, nullptr, nullptr, cBT, cE, cE, 0, 0);
    }
    // 3) gx = enc2 @ w_ih^T + (b_ih + b_hh), stored [T,B,4H]
    {
        dim3 grid(cG/128, cBT/128);
        sgemm_k<128,128,16,8,8,true,2><<<grid, 256>>>(
            enc2, w_ih, gx, b_ih, b_hh, nullptr, cBT, cG, cE, cT, cB);
    }
    // 4) LSTM scan
    {
        const float* hin = h0;
        const float* cin = c0;
        dim3 ggrid(cG/128, cB/64);
        int cellBlocks = (cB * cH + 255) / 256;
        for (int t = 0; t < cT; ++t) {
            sgemm_k<64,128,16,4,8,true,3><<<ggrid, 256>>>(
                hin, w_hh, gates, nullptr, nullptr,
                gx + (size_t)t * cB * cG, cB, cG, cH, 0, 0);
            float* hout = hbuf[t & 1];
            float* cout = cbuf[t & 1];
            lstm_cell_k<<<cellBlocks, 256>>>(gates, cin, cout, hout, hseq, t);
            hin = hout;
            cin = cout;
        }
        // final h/c -> d_out
        copy2_k<<<(cB*cH + 255)/256, 256>>>(hin, cin, out + OFF_HT, out + OFF_CT, cB*cH);
    }
    // 5) x = layernorm(hseq)  (reuse enc1 as x)
    layernorm_k<<<cBT, 256>>>(hseq, enc1, ln_g, ln_b);
    // 6) logits = x @ Wa + ba   [32768,1024]x[1024,64]
    {
        dim3 grid(cA/64, cBT/128);
        sgemm_k<128,64,16,8,4,false,0><<<grid, 256>>>(
            enc1, Wa, out + OFF_LOGITS, ba, nullptr, nullptr, cBT, cA, cH, 0, 0);
    }
    // 7) obs_pred = x @ Wobs + bobs  [32768,1024]x[1024,512]
    {
        dim3 grid(cOBS/128, cBT/128);
        sgemm_k<128,128,16,8,8,false,0><<<grid, 256>>>(
            enc1, Wobs, out + OFF_OBS, bobs, nullptr, nullptr, cBT, cOBS, cH, 0, 0);
    }
    // 8) values / rew_pred (dual GEMV)
    dual_gemv_k<<<(cBT*32 + 255)/256, 256>>>(
        enc1, Wc, Wr, bc, br, out + OFF_VAL, out + OFF_REW);
}